// round 1
// baseline (speedup 1.0000x reference)
#include <cuda_runtime.h>
#include <math.h>

#define BB 16
#define NN 1024
#define CC 768
#define NH 12
#define HD 64
#define ROWS (BB*NN)        // 16384

// ---------------- device scratch ----------------
__device__ float g_h[ROWS*CC];          // h (LN1 out), reused as h2
__device__ float g_qkv[ROWS*3*CC];      // qkv projections
__device__ float g_eta[BB*NH*NN];       // eta[b][h][n]
__device__ float g_attn[ROWS*CC];       // attn output (B,N,C)
__device__ float g_x2[ROWS*CC];         // x after proj residual
__device__ float g_act[ROWS*4*CC];      // gelu(fc1) activations
__device__ float g_qkvbias[3*CC];

// ---------------- helpers ----------------
__device__ __forceinline__ float warpsum(float v) {
#pragma unroll
    for (int o = 16; o > 0; o >>= 1) v += __shfl_xor_sync(0xffffffffu, v, o);
    return v;
}

// ---------------- qkv bias build ----------------
__global__ void qkvbias_kernel(const float* __restrict__ qb,
                               const float* __restrict__ vb,
                               float* __restrict__ out) {
    int i = blockIdx.x * blockDim.x + threadIdx.x;
    if (i < 3*CC) out[i] = (i < CC) ? qb[i] : (i < 2*CC ? 0.0f : vb[i - 2*CC]);
}

// ---------------- LayerNorm (+ optional eta) ----------------
// one block per row, 256 threads, each thread owns cols {t, t+256, t+512}
__global__ void __launch_bounds__(256) ln_kernel(
    const float* __restrict__ x, const float* __restrict__ w, const float* __restrict__ bp,
    const float* __restrict__ lrw, const float* __restrict__ lrb,
    float* __restrict__ hout, float* __restrict__ eta)
{
    __shared__ float redA[8], redB[8], pr[8*NH];
    int row = blockIdx.x;
    int tid = threadIdx.x, lane = tid & 31, warp = tid >> 5;
    const float* xr = x + (size_t)row * CC;
    float v0 = xr[tid], v1 = xr[tid+256], v2 = xr[tid+512];

    float s = warpsum(v0+v1+v2);
    if (lane == 0) redA[warp] = s;
    __syncthreads();
    float tot = 0.f;
#pragma unroll
    for (int i = 0; i < 8; i++) tot += redA[i];
    float mu = tot * (1.0f/CC);
    float d0 = v0-mu, d1 = v1-mu, d2 = v2-mu;
    float vsum = warpsum(d0*d0 + d1*d1 + d2*d2);
    if (lane == 0) redB[warp] = vsum;
    __syncthreads();
    float var = 0.f;
#pragma unroll
    for (int i = 0; i < 8; i++) var += redB[i];
    var *= (1.0f/CC);
    float rstd = rsqrtf(var + 1e-6f);

    float h0 = w[tid    ]*d0*rstd + bp[tid    ];
    float h1 = w[tid+256]*d1*rstd + bp[tid+256];
    float h2 = w[tid+512]*d2*rstd + bp[tid+512];
    float* hr = hout + (size_t)row * CC;
    hr[tid] = h0; hr[tid+256] = h1; hr[tid+512] = h2;

    if (eta) {
        float p[NH];
#pragma unroll
        for (int hh = 0; hh < NH; hh++) {
            const float* lw = lrw + (size_t)hh * CC;
            p[hh] = h0*lw[tid] + h1*lw[tid+256] + h2*lw[tid+512];
        }
#pragma unroll
        for (int hh = 0; hh < NH; hh++) {
            float ps = warpsum(p[hh]);
            if (lane == 0) pr[warp*NH + hh] = ps;
        }
        __syncthreads();
        if (tid < NH) {
            float ss = 0.f;
#pragma unroll
            for (int wv = 0; wv < 8; wv++) ss += pr[wv*NH + tid];
            ss += lrb[tid];
            float sg = 1.0f / (1.0f + expf(-ss));
            int b = row >> 10, n = row & 1023;
            eta[((size_t)(b*NH + tid))*NN + n] = sg * (1.0f/HD);
        }
    }
}

// ---------------- SGEMM NT: C[M,N] = act(A[M,K] @ B[N,K]^T + bias) (+ Res) ----------------
// 128x128 tile, BK=8, 256 threads, 8x8 per thread
template<int ACT>
__global__ void __launch_bounds__(256) sgemm_nt(
    const float* __restrict__ A, const float* __restrict__ Bw,
    const float* __restrict__ bias, const float* __restrict__ Res,
    float* __restrict__ C, int M, int Nn, int K)
{
    __shared__ float As[8][128];
    __shared__ float Bs[8][128];
    int bn = blockIdx.x * 128;
    int bm = blockIdx.y * 128;
    int tid = threadIdx.x;
    int lr = tid >> 1;            // 0..127
    int lc = (tid & 1) * 4;       // 0 or 4
    const float* Aload = A + (size_t)(bm + lr) * K + lc;
    const float* Bload = Bw + (size_t)(bn + lr) * K + lc;
    int tx = tid & 15, ty = tid >> 4;

    float acc[8][8];
#pragma unroll
    for (int i = 0; i < 8; i++)
#pragma unroll
        for (int j = 0; j < 8; j++) acc[i][j] = 0.f;

    for (int k0 = 0; k0 < K; k0 += 8) {
        float4 a = *(const float4*)(Aload + k0);
        float4 bv = *(const float4*)(Bload + k0);
        As[lc+0][lr] = a.x;  As[lc+1][lr] = a.y;  As[lc+2][lr] = a.z;  As[lc+3][lr] = a.w;
        Bs[lc+0][lr] = bv.x; Bs[lc+1][lr] = bv.y; Bs[lc+2][lr] = bv.z; Bs[lc+3][lr] = bv.w;
        __syncthreads();
#pragma unroll
        for (int kk = 0; kk < 8; kk++) {
            float4 a0 = *(const float4*)&As[kk][ty*8];
            float4 a1 = *(const float4*)&As[kk][ty*8+4];
            float4 b0 = *(const float4*)&Bs[kk][tx*8];
            float4 b1 = *(const float4*)&Bs[kk][tx*8+4];
            float ra[8] = {a0.x,a0.y,a0.z,a0.w,a1.x,a1.y,a1.z,a1.w};
            float rb[8] = {b0.x,b0.y,b0.z,b0.w,b1.x,b1.y,b1.z,b1.w};
#pragma unroll
            for (int i = 0; i < 8; i++)
#pragma unroll
                for (int j = 0; j < 8; j++) acc[i][j] += ra[i]*rb[j];
        }
        __syncthreads();
    }

#pragma unroll
    for (int i = 0; i < 8; i++) {
        int m = bm + ty*8 + i;
        size_t rbase = (size_t)m * Nn;
#pragma unroll
        for (int j = 0; j < 8; j++) {
            int n = bn + tx*8 + j;
            float c = acc[i][j] + bias[n];
            if (ACT == 1) c = 0.5f * c * (1.0f + erff(c * 0.70710678118654752f));
            if (Res) c += Res[rbase + n];
            C[rbase + n] = c;
        }
    }
}

// ---------------- TTT kernel: one block per (b,h) ----------------
// dynamic smem: W1(4096) K(4096) V(4096) Z(4096) eta(64) gw(64) gb(64) b1(64) b1b(64) bred(256)
__global__ void __launch_bounds__(256) ttt_kernel(
    const float* __restrict__ qkv, const float* __restrict__ eta,
    const float* __restrict__ W1g, const float* __restrict__ b1g,
    const float* __restrict__ tttw, const float* __restrict__ tttb,
    float* __restrict__ attn)
{
    extern __shared__ float sm[];
    float* sW1  = sm;            // 4096 (becomes W1_bar)
    float* sK   = sm + 4096;     // k / q chunk
    float* sV   = sm + 8192;     // v chunk
    float* sZ   = sm + 12288;    // Z1 / eg / Z
    float* sEta = sm + 16384;    // 64
    float* sGw  = sEta + 64;
    float* sGb  = sGw + 64;
    float* sB1  = sGb + 64;
    float* sB1b = sB1 + 64;
    float* sBred= sB1b + 64;     // 256

    int bh = blockIdx.x;
    int b = bh / NH, h = bh % NH;
    int tid = threadIdx.x, tx = tid & 63, ty = tid >> 6;
    int lane = tid & 31, warp = tid >> 5;

    for (int i = tid; i < 4096; i += 256) sW1[i] = W1g[h*4096 + i];
    if (tid < 64) {
        sGw[tid] = tttw[h*64 + tid];
        sGb[tid] = tttb[h*64 + tid];
        sB1[tid] = b1g[h*64 + tid];
    }
    __syncthreads();

    const size_t rs = 3*CC;
    const float* qbase = qkv + (size_t)b*NN*rs + 0*CC + h*HD;
    const float* kbase = qkv + (size_t)b*NN*rs + 1*CC + h*HD;
    const float* vbase = qkv + (size_t)b*NN*rs + 2*CC + h*HD;

    float accW[16];
#pragma unroll
    for (int i = 0; i < 16; i++) accW[i] = 0.f;
    float accB = 0.f;

    for (int c = 0; c < 16; c++) {
        int n0 = c * 64;
        for (int i = tid; i < 4096; i += 256) {
            int n = i >> 6, e = i & 63;
            sK[i] = kbase[(size_t)(n0+n)*rs + e];
            sV[i] = vbase[(size_t)(n0+n)*rs + e];
        }
        if (tid < 64) sEta[tid] = eta[(size_t)bh*NN + n0 + tid];
        __syncthreads();

        // Z1 = K @ W1 + b1
        {
            float az[16];
#pragma unroll
            for (int i = 0; i < 16; i++) az[i] = sB1[tx];
            for (int d = 0; d < 64; d++) {
                float w = sW1[d*64 + tx];
#pragma unroll
                for (int i = 0; i < 16; i++) az[i] += sK[(i*4 + ty)*64 + d] * w;
            }
#pragma unroll
            for (int i = 0; i < 16; i++) sZ[(i*4 + ty)*64 + tx] = az[i];
        }
        __syncthreads();

        // fused LN-L2 backward, eg = eta*grad -> sZ
        for (int j = 0; j < 8; j++) {
            int n = warp + 8*j;
            float z0 = sZ[n*64 + lane], z1 = sZ[n*64 + lane + 32];
            float mu = warpsum(z0 + z1) * (1.0f/64);
            float d0 = z0 - mu, d1 = z1 - mu;
            float var = warpsum(d0*d0 + d1*d1) * (1.0f/64);
            float rstd = rsqrtf(var + 1e-6f);
            float xh0 = d0*rstd, xh1 = d1*rstd;
            float t0 = sV[n*64 + lane]      - sK[n*64 + lane];
            float t1 = sV[n*64 + lane + 32] - sK[n*64 + lane + 32];
            float g0 = sGw[lane], g1 = sGw[lane + 32];
            float gho0 = (g0*xh0 + sGb[lane]      - t0) * g0;
            float gho1 = (g1*xh1 + sGb[lane + 32] - t1) * g1;
            float sg  = warpsum(gho0 + gho1);
            float sgx = warpsum(gho0*xh0 + gho1*xh1);
            float e = sEta[n];
            float inv = rstd * (1.0f/64) * e;
            sZ[n*64 + lane]      = (64.f*gho0 - sg - xh0*sgx) * inv;
            sZ[n*64 + lane + 32] = (64.f*gho1 - sg - xh1*sgx) * inv;
        }
        __syncthreads();

        // accW[d][e] += sum_n K[n][d]*eg[n][e];  accB += sum_n eg[n][e]
        for (int n = 0; n < 64; n++) {
            float z = sZ[n*64 + tx];
            const float* kr = &sK[n*64 + ty*16];
#pragma unroll
            for (int i = 0; i < 16; i++) accW[i] += kr[i] * z;
            if ((n >> 4) == ty) accB += z;
        }
        __syncthreads();
    }

    // W1_bar in place; b1_bar
#pragma unroll
    for (int i = 0; i < 16; i++) sW1[(ty*16 + i)*64 + tx] -= accW[i];
    sBred[ty*64 + tx] = accB;
    __syncthreads();
    if (ty == 0)
        sB1b[tx] = sB1[tx] - (sBred[tx] + sBred[64+tx] + sBred[128+tx] + sBred[192+tx]);
    __syncthreads();

    // pass 2: Z = Q @ W1_bar + b1_bar ; out = q + LN(Z)
    for (int c = 0; c < 16; c++) {
        int n0 = c * 64;
        for (int i = tid; i < 4096; i += 256) {
            int n = i >> 6, e = i & 63;
            sK[i] = qbase[(size_t)(n0+n)*rs + e];
        }
        __syncthreads();
        {
            float az[16];
#pragma unroll
            for (int i = 0; i < 16; i++) az[i] = sB1b[tx];
            for (int d = 0; d < 64; d++) {
                float w = sW1[d*64 + tx];
#pragma unroll
                for (int i = 0; i < 16; i++) az[i] += sK[(i*4 + ty)*64 + d] * w;
            }
#pragma unroll
            for (int i = 0; i < 16; i++) sZ[(i*4 + ty)*64 + tx] = az[i];
        }
        __syncthreads();
        for (int j = 0; j < 8; j++) {
            int n = warp + 8*j;
            float z0 = sZ[n*64 + lane], z1 = sZ[n*64 + lane + 32];
            float mu = warpsum(z0 + z1) * (1.0f/64);
            float d0 = z0 - mu, d1 = z1 - mu;
            float var = warpsum(d0*d0 + d1*d1) * (1.0f/64);
            float rstd = rsqrtf(var + 1e-6f);
            float o0 = sK[n*64 + lane]      + sGw[lane]     *d0*rstd + sGb[lane];
            float o1 = sK[n*64 + lane + 32] + sGw[lane + 32]*d1*rstd + sGb[lane + 32];
            size_t orow = ((size_t)(b*NN + n0 + n))*CC + h*HD;
            attn[orow + lane]      = o0;
            attn[orow + lane + 32] = o1;
        }
        __syncthreads();
    }
}

// ---------------- launch ----------------
extern "C" void kernel_launch(void* const* d_in, const int* in_sizes, int n_in,
                              void* d_out, int out_size) {
    const float* x      = (const float*)d_in[0];
    const float* qkv_w  = (const float*)d_in[1];
    const float* q_bias = (const float*)d_in[2];
    const float* v_bias = (const float*)d_in[3];
    const float* proj_w = (const float*)d_in[4];
    const float* proj_b = (const float*)d_in[5];
    const float* lr_w   = (const float*)d_in[6];
    const float* lr_b   = (const float*)d_in[7];
    const float* W1     = (const float*)d_in[8];
    const float* b1     = (const float*)d_in[9];
    const float* ttt_w  = (const float*)d_in[10];
    const float* ttt_b  = (const float*)d_in[11];
    const float* n1w    = (const float*)d_in[12];
    const float* n1b    = (const float*)d_in[13];
    const float* n2w    = (const float*)d_in[14];
    const float* n2b    = (const float*)d_in[15];
    const float* fc1_w  = (const float*)d_in[16];
    const float* fc1_b  = (const float*)d_in[17];
    const float* fc2_w  = (const float*)d_in[18];
    const float* fc2_b  = (const float*)d_in[19];
    float* out = (float*)d_out;

    float *h, *qkvb, *etap, *attn, *x2, *act, *qbias;
    cudaGetSymbolAddress((void**)&h,    g_h);
    cudaGetSymbolAddress((void**)&qkvb, g_qkv);
    cudaGetSymbolAddress((void**)&etap, g_eta);
    cudaGetSymbolAddress((void**)&attn, g_attn);
    cudaGetSymbolAddress((void**)&x2,   g_x2);
    cudaGetSymbolAddress((void**)&act,  g_act);
    cudaGetSymbolAddress((void**)&qbias,g_qkvbias);

    const int TTT_SMEM = (16384 + 64*5 + 256) * 4;  // ~67.8 KB
    cudaFuncSetAttribute(ttt_kernel, cudaFuncAttributeMaxDynamicSharedMemorySize, TTT_SMEM);

    qkvbias_kernel<<<(3*CC + 255)/256, 256>>>(q_bias, v_bias, qbias);
    ln_kernel<<<ROWS, 256>>>(x, n1w, n1b, lr_w, lr_b, h, etap);
    sgemm_nt<0><<<dim3(3*CC/128, ROWS/128), 256>>>(h, qkv_w, qbias, nullptr, qkvb, ROWS, 3*CC, CC);
    ttt_kernel<<<BB*NH, 256, TTT_SMEM>>>(qkvb, etap, W1, b1, ttt_w, ttt_b, attn);
    sgemm_nt<0><<<dim3(CC/128, ROWS/128), 256>>>(attn, proj_w, proj_b, x, x2, ROWS, CC, CC);
    ln_kernel<<<ROWS, 256>>>(x2, n2w, n2b, nullptr, nullptr, h, nullptr);
    sgemm_nt<1><<<dim3(4*CC/128, ROWS/128), 256>>>(h, fc1_w, fc1_b, nullptr, act, ROWS, 4*CC, CC);
    sgemm_nt<0><<<dim3(CC/128, ROWS/128), 256>>>(act, fc2_w, fc2_b, x2, out, ROWS, CC, 4*CC);
}

// round 4
// speedup vs baseline: 1.9593x; 1.9593x over previous
#include <cuda_runtime.h>
#include <cuda_bf16.h>
#include <math.h>
#include <stdint.h>

#define BB 16
#define NN 1024
#define CC 768
#define NH 12
#define HD 64
#define ROWS (BB*NN)        // 16384

// GEMM tiling (mma.sync path)
#define BM 128
#define BN 128
#define BKC 32              // k elements per chunk
#define PITCH 36            // smem row pitch (bf16 elems) -> conflict-free frag loads

// ---------------- device scratch ----------------
__device__ float    g_qkv[ROWS*3*CC];      // qkv projections fp32
__device__ float    g_eta[BB*NH*NN];
__device__ float    g_x2[ROWS*CC];         // x after proj residual (fp32)
__device__ float    g_qkvbias[3*CC];
__device__ uint32_t g_hp[ROWS*CC];         // h / h2 packed (hi<<16|lo)
__device__ uint32_t g_attnp[ROWS*CC];      // attn packed
__device__ uint32_t g_actp[ROWS*4*CC];     // gelu(fc1) packed
__device__ uint32_t g_wqp[3*CC*CC];
__device__ uint32_t g_wpp[CC*CC];
__device__ uint32_t g_w1p[4*CC*CC];
__device__ uint32_t g_w2p[CC*4*CC];

// ---------------- helpers ----------------
__device__ __forceinline__ float warpsum(float v) {
#pragma unroll
    for (int o = 16; o > 0; o >>= 1) v += __shfl_xor_sync(0xffffffffu, v, o);
    return v;
}
__device__ __forceinline__ uint32_t pack2(float v) {
    unsigned short hs = __bfloat16_as_ushort(__float2bfloat16(v));
    float hf = __bfloat162float(__ushort_as_bfloat16(hs));
    unsigned short ls = __bfloat16_as_ushort(__float2bfloat16(v - hf));
    return ((uint32_t)hs << 16) | (uint32_t)ls;
}
__device__ __forceinline__ void mma16816(float* d, const uint32_t* a, const uint32_t* b) {
    asm volatile(
        "mma.sync.aligned.m16n8k16.row.col.f32.bf16.bf16.f32 "
        "{%0,%1,%2,%3}, {%4,%5,%6,%7}, {%8,%9}, {%0,%1,%2,%3};"
        : "+f"(d[0]), "+f"(d[1]), "+f"(d[2]), "+f"(d[3])
        : "r"(a[0]), "r"(a[1]), "r"(a[2]), "r"(a[3]), "r"(b[0]), "r"(b[1]));
}

// ---------------- small elementwise kernels ----------------
__global__ void qkvbias_kernel(const float* __restrict__ qb,
                               const float* __restrict__ vb,
                               float* __restrict__ out) {
    int i = blockIdx.x * blockDim.x + threadIdx.x;
    if (i < 3*CC) out[i] = (i < CC) ? qb[i] : (i < 2*CC ? 0.0f : vb[i - 2*CC]);
}
__global__ void convert_pack(const float* __restrict__ in, uint32_t* __restrict__ out, int n) {
    int i = blockIdx.x * blockDim.x + threadIdx.x;
    if (i < n) out[i] = pack2(in[i]);
}

// ---------------- LayerNorm (+ optional eta), packed output ----------------
__global__ void __launch_bounds__(256) ln_kernel(
    const float* __restrict__ x, const float* __restrict__ w, const float* __restrict__ bp,
    const float* __restrict__ lrw, const float* __restrict__ lrb,
    uint32_t* __restrict__ hout, float* __restrict__ eta)
{
    __shared__ float redA[8], redB[8], pr[8*NH];
    int row = blockIdx.x;
    int tid = threadIdx.x, lane = tid & 31, warp = tid >> 5;
    const float* xr = x + (size_t)row * CC;
    float v0 = xr[tid], v1 = xr[tid+256], v2 = xr[tid+512];

    float s = warpsum(v0+v1+v2);
    if (lane == 0) redA[warp] = s;
    __syncthreads();
    float tot = 0.f;
#pragma unroll
    for (int i = 0; i < 8; i++) tot += redA[i];
    float mu = tot * (1.0f/CC);
    float d0 = v0-mu, d1 = v1-mu, d2 = v2-mu;
    float vsum = warpsum(d0*d0 + d1*d1 + d2*d2);
    if (lane == 0) redB[warp] = vsum;
    __syncthreads();
    float var = 0.f;
#pragma unroll
    for (int i = 0; i < 8; i++) var += redB[i];
    var *= (1.0f/CC);
    float rstd = rsqrtf(var + 1e-6f);

    float h0 = w[tid    ]*d0*rstd + bp[tid    ];
    float h1 = w[tid+256]*d1*rstd + bp[tid+256];
    float h2 = w[tid+512]*d2*rstd + bp[tid+512];
    uint32_t* hr = hout + (size_t)row * CC;
    hr[tid] = pack2(h0); hr[tid+256] = pack2(h1); hr[tid+512] = pack2(h2);

    if (eta) {
        float p[NH];
#pragma unroll
        for (int hh = 0; hh < NH; hh++) {
            const float* lw = lrw + (size_t)hh * CC;
            p[hh] = h0*lw[tid] + h1*lw[tid+256] + h2*lw[tid+512];
        }
#pragma unroll
        for (int hh = 0; hh < NH; hh++) {
            float ps = warpsum(p[hh]);
            if (lane == 0) pr[warp*NH + hh] = ps;
        }
        __syncthreads();
        if (tid < NH) {
            float ss = 0.f;
#pragma unroll
            for (int wv = 0; wv < 8; wv++) ss += pr[wv*NH + tid];
            ss += lrb[tid];
            float sg = 1.0f / (1.0f + expf(-ss));
            int b = row >> 10, n = row & 1023;
            eta[((size_t)(b*NH + tid))*NN + n] = sg * (1.0f/HD);
        }
    }
}

// ---------------- mma.sync split-bf16 GEMM NT ----------------
// C[M,Nn] = epi(A[M,K] @ B[Nn,K]^T + bias), A/B packed (hi<<16|lo)
// EPI: 0 = fp32 out; 1 = +Res fp32 out; 2 = gelu packed out
template<int EPI>
__global__ void __launch_bounds__(256, 1) gemm_mma(
    const uint4* __restrict__ A, const uint4* __restrict__ Bw,
    const float* __restrict__ bias, const float* __restrict__ Res,
    float* __restrict__ Cout, uint32_t* __restrict__ CoutP,
    int M, int Nn, int K)
{
    __shared__ unsigned short sAhi[128*PITCH], sAlo[128*PITCH];
    __shared__ unsigned short sBhi[128*PITCH], sBlo[128*PITCH];

    int tid = threadIdx.x;
    int lane = tid & 31, wid = tid >> 5;
    int wm = wid & 1, wn = wid >> 1;          // 2x4 warp grid, warp tile 64x32
    int g = lane >> 2, t4 = lane & 3;
    int bn = blockIdx.x * BN, bm = blockIdx.y * BM;

    const int K4 = K >> 2;
    const int nch = K / BKC;

    float acc[4][4][4];
#pragma unroll
    for (int i = 0; i < 4; i++)
#pragma unroll
        for (int j = 0; j < 4; j++)
#pragma unroll
            for (int k = 0; k < 4; k++) acc[i][j][k] = 0.f;

    uint4 ra[4], rb[4];
    // preload chunk 0
#pragma unroll
    for (int i = 0; i < 4; i++) {
        int idx = tid + i*256;
        int row = idx >> 3, q = idx & 7;
        ra[i] = A [(size_t)(bm + row)*K4 + q];
        rb[i] = Bw[(size_t)(bn + row)*K4 + q];
    }

    for (int c = 0; c < nch; ++c) {
        __syncthreads();
        // split + store to smem
#pragma unroll
        for (int i = 0; i < 4; i++) {
            int idx = tid + i*256;
            int row = idx >> 3, q = idx & 7;
            uint4 v = ra[i];
            *(uint2*)&sAhi[row*PITCH + q*4] =
                make_uint2(__byte_perm(v.x, v.y, 0x7632), __byte_perm(v.z, v.w, 0x7632));
            *(uint2*)&sAlo[row*PITCH + q*4] =
                make_uint2(__byte_perm(v.x, v.y, 0x5410), __byte_perm(v.z, v.w, 0x5410));
            v = rb[i];
            *(uint2*)&sBhi[row*PITCH + q*4] =
                make_uint2(__byte_perm(v.x, v.y, 0x7632), __byte_perm(v.z, v.w, 0x7632));
            *(uint2*)&sBlo[row*PITCH + q*4] =
                make_uint2(__byte_perm(v.x, v.y, 0x5410), __byte_perm(v.z, v.w, 0x5410));
        }
        __syncthreads();
        // prefetch next chunk
        if (c + 1 < nch) {
            int k4 = (c + 1) * (BKC/4);
#pragma unroll
            for (int i = 0; i < 4; i++) {
                int idx = tid + i*256;
                int row = idx >> 3, q = idx & 7;
                ra[i] = A [(size_t)(bm + row)*K4 + k4 + q];
                rb[i] = Bw[(size_t)(bn + row)*K4 + k4 + q];
            }
        }
        // compute on smem chunk
#pragma unroll
        for (int ks = 0; ks < 2; ks++) {
            int kof = ks*16 + t4*2;
            uint32_t ah[4][4], al[4][4], bh[4][2], bl[4][2];
#pragma unroll
            for (int mt = 0; mt < 4; mt++) {
                int base = (wm*64 + mt*16 + g)*PITCH + kof;
                ah[mt][0] = *(const uint32_t*)&sAhi[base];
                ah[mt][1] = *(const uint32_t*)&sAhi[base + 8*PITCH];
                ah[mt][2] = *(const uint32_t*)&sAhi[base + 8];
                ah[mt][3] = *(const uint32_t*)&sAhi[base + 8*PITCH + 8];
                al[mt][0] = *(const uint32_t*)&sAlo[base];
                al[mt][1] = *(const uint32_t*)&sAlo[base + 8*PITCH];
                al[mt][2] = *(const uint32_t*)&sAlo[base + 8];
                al[mt][3] = *(const uint32_t*)&sAlo[base + 8*PITCH + 8];
            }
#pragma unroll
            for (int nt = 0; nt < 4; nt++) {
                int base = (wn*32 + nt*8 + g)*PITCH + kof;
                bh[nt][0] = *(const uint32_t*)&sBhi[base];
                bh[nt][1] = *(const uint32_t*)&sBhi[base + 8];
                bl[nt][0] = *(const uint32_t*)&sBlo[base];
                bl[nt][1] = *(const uint32_t*)&sBlo[base + 8];
            }
#pragma unroll
            for (int mt = 0; mt < 4; mt++)
#pragma unroll
                for (int nt = 0; nt < 4; nt++) {
                    mma16816(acc[mt][nt], ah[mt], bh[nt]);
                    mma16816(acc[mt][nt], ah[mt], bl[nt]);
                    mma16816(acc[mt][nt], al[mt], bh[nt]);
                }
        }
    }

    // epilogue: direct register -> global
#pragma unroll
    for (int mt = 0; mt < 4; mt++) {
#pragma unroll
        for (int nt = 0; nt < 4; nt++) {
            int r0 = bm + wm*64 + mt*16 + g;
            int c0 = bn + wn*32 + nt*8 + t4*2;
            float b0 = bias[c0], b1 = bias[c0+1];
#pragma unroll
            for (int half = 0; half < 2; half++) {
                int r = r0 + half*8;
                size_t gi = (size_t)r * Nn + c0;
                float v0 = acc[mt][nt][half*2]     + b0;
                float v1 = acc[mt][nt][half*2 + 1] + b1;
                if (EPI == 1) { v0 += Res[gi]; v1 += Res[gi+1]; }
                if (EPI == 2) {
                    v0 = 0.5f*v0*(1.0f + erff(v0*0.70710678118654752f));
                    v1 = 0.5f*v1*(1.0f + erff(v1*0.70710678118654752f));
                    CoutP[gi]   = pack2(v0);
                    CoutP[gi+1] = pack2(v1);
                } else {
                    Cout[gi]   = v0;
                    Cout[gi+1] = v1;
                }
            }
        }
    }
}

// ---------------- TTT kernel: one block per (b,h) ----------------
__global__ void __launch_bounds__(256) ttt_kernel(
    const float* __restrict__ qkv, const float* __restrict__ eta,
    const float* __restrict__ W1g, const float* __restrict__ b1g,
    const float* __restrict__ tttw, const float* __restrict__ tttb,
    uint32_t* __restrict__ attn)
{
    extern __shared__ float sm[];
    float* sW1  = sm;            // 4096 (becomes W1_bar)
    float* sK   = sm + 4096;
    float* sV   = sm + 8192;
    float* sZ   = sm + 12288;
    float* sEta = sm + 16384;    // 64
    float* sGw  = sEta + 64;
    float* sGb  = sGw + 64;
    float* sB1  = sGb + 64;
    float* sB1b = sB1 + 64;
    float* sBred= sB1b + 64;     // 256

    int bh = blockIdx.x;
    int b = bh / NH, h = bh % NH;
    int tid = threadIdx.x, tx = tid & 63, ty = tid >> 6;
    int lane = tid & 31, warp = tid >> 5;

    for (int i = tid; i < 4096; i += 256) sW1[i] = W1g[h*4096 + i];
    if (tid < 64) {
        sGw[tid] = tttw[h*64 + tid];
        sGb[tid] = tttb[h*64 + tid];
        sB1[tid] = b1g[h*64 + tid];
    }
    __syncthreads();

    const size_t rs = 3*CC;
    const float* qbase = qkv + (size_t)b*NN*rs + 0*CC + h*HD;
    const float* kbase = qkv + (size_t)b*NN*rs + 1*CC + h*HD;
    const float* vbase = qkv + (size_t)b*NN*rs + 2*CC + h*HD;

    float accW[16];
#pragma unroll
    for (int i = 0; i < 16; i++) accW[i] = 0.f;
    float accB = 0.f;

    for (int c = 0; c < 16; c++) {
        int n0 = c * 64;
        for (int i = tid; i < 4096; i += 256) {
            int n = i >> 6, e = i & 63;
            sK[i] = kbase[(size_t)(n0+n)*rs + e];
            sV[i] = vbase[(size_t)(n0+n)*rs + e];
        }
        if (tid < 64) sEta[tid] = eta[(size_t)bh*NN + n0 + tid];
        __syncthreads();

        {
            float az[16];
#pragma unroll
            for (int i = 0; i < 16; i++) az[i] = sB1[tx];
            for (int d = 0; d < 64; d++) {
                float w = sW1[d*64 + tx];
#pragma unroll
                for (int i = 0; i < 16; i++) az[i] += sK[(i*4 + ty)*64 + d] * w;
            }
#pragma unroll
            for (int i = 0; i < 16; i++) sZ[(i*4 + ty)*64 + tx] = az[i];
        }
        __syncthreads();

        for (int j = 0; j < 8; j++) {
            int n = warp + 8*j;
            float z0 = sZ[n*64 + lane], z1 = sZ[n*64 + lane + 32];
            float mu = warpsum(z0 + z1) * (1.0f/64);
            float d0 = z0 - mu, d1 = z1 - mu;
            float var = warpsum(d0*d0 + d1*d1) * (1.0f/64);
            float rstd = rsqrtf(var + 1e-6f);
            float xh0 = d0*rstd, xh1 = d1*rstd;
            float t0 = sV[n*64 + lane]      - sK[n*64 + lane];
            float t1 = sV[n*64 + lane + 32] - sK[n*64 + lane + 32];
            float g0 = sGw[lane], g1 = sGw[lane + 32];
            float gho0 = (g0*xh0 + sGb[lane]      - t0) * g0;
            float gho1 = (g1*xh1 + sGb[lane + 32] - t1) * g1;
            float sg  = warpsum(gho0 + gho1);
            float sgx = warpsum(gho0*xh0 + gho1*xh1);
            float e = sEta[n];
            float inv = rstd * (1.0f/64) * e;
            sZ[n*64 + lane]      = (64.f*gho0 - sg - xh0*sgx) * inv;
            sZ[n*64 + lane + 32] = (64.f*gho1 - sg - xh1*sgx) * inv;
        }
        __syncthreads();

        for (int n = 0; n < 64; n++) {
            float z = sZ[n*64 + tx];
            const float* kr = &sK[n*64 + ty*16];
#pragma unroll
            for (int i = 0; i < 16; i++) accW[i] += kr[i] * z;
            if ((n >> 4) == ty) accB += z;
        }
        __syncthreads();
    }

#pragma unroll
    for (int i = 0; i < 16; i++) sW1[(ty*16 + i)*64 + tx] -= accW[i];
    sBred[ty*64 + tx] = accB;
    __syncthreads();
    if (ty == 0)
        sB1b[tx] = sB1[tx] - (sBred[tx] + sBred[64+tx] + sBred[128+tx] + sBred[192+tx]);
    __syncthreads();

    for (int c = 0; c < 16; c++) {
        int n0 = c * 64;
        for (int i = tid; i < 4096; i += 256) {
            int n = i >> 6, e = i & 63;
            sK[i] = qbase[(size_t)(n0+n)*rs + e];
        }
        __syncthreads();
        {
            float az[16];
#pragma unroll
            for (int i = 0; i < 16; i++) az[i] = sB1b[tx];
            for (int d = 0; d < 64; d++) {
                float w = sW1[d*64 + tx];
#pragma unroll
                for (int i = 0; i < 16; i++) az[i] += sK[(i*4 + ty)*64 + d] * w;
            }
#pragma unroll
            for (int i = 0; i < 16; i++) sZ[(i*4 + ty)*64 + tx] = az[i];
        }
        __syncthreads();
        for (int j = 0; j < 8; j++) {
            int n = warp + 8*j;
            float z0 = sZ[n*64 + lane], z1 = sZ[n*64 + lane + 32];
            float mu = warpsum(z0 + z1) * (1.0f/64);
            float d0 = z0 - mu, d1 = z1 - mu;
            float var = warpsum(d0*d0 + d1*d1) * (1.0f/64);
            float rstd = rsqrtf(var + 1e-6f);
            float o0 = sK[n*64 + lane]      + sGw[lane]     *d0*rstd + sGb[lane];
            float o1 = sK[n*64 + lane + 32] + sGw[lane + 32]*d1*rstd + sGb[lane + 32];
            size_t orow = ((size_t)(b*NN + n0 + n))*CC + h*HD;
            attn[orow + lane]      = pack2(o0);
            attn[orow + lane + 32] = pack2(o1);
        }
        __syncthreads();
    }
}

// ---------------- launch ----------------
extern "C" void kernel_launch(void* const* d_in, const int* in_sizes, int n_in,
                              void* d_out, int out_size) {
    const float* x      = (const float*)d_in[0];
    const float* qkv_w  = (const float*)d_in[1];
    const float* q_bias = (const float*)d_in[2];
    const float* v_bias = (const float*)d_in[3];
    const float* proj_w = (const float*)d_in[4];
    const float* proj_b = (const float*)d_in[5];
    const float* lr_w   = (const float*)d_in[6];
    const float* lr_b   = (const float*)d_in[7];
    const float* W1     = (const float*)d_in[8];
    const float* b1     = (const float*)d_in[9];
    const float* ttt_w  = (const float*)d_in[10];
    const float* ttt_b  = (const float*)d_in[11];
    const float* n1w    = (const float*)d_in[12];
    const float* n1b    = (const float*)d_in[13];
    const float* n2w    = (const float*)d_in[14];
    const float* n2b    = (const float*)d_in[15];
    const float* fc1_w  = (const float*)d_in[16];
    const float* fc1_b  = (const float*)d_in[17];
    const float* fc2_w  = (const float*)d_in[18];
    const float* fc2_b  = (const float*)d_in[19];
    float* out = (float*)d_out;

    float *qkvb, *etap, *x2, *qbias;
    uint32_t *hp, *attnp, *actp, *wqp, *wpp, *w1p, *w2p;
    cudaGetSymbolAddress((void**)&qkvb,  g_qkv);
    cudaGetSymbolAddress((void**)&etap,  g_eta);
    cudaGetSymbolAddress((void**)&x2,    g_x2);
    cudaGetSymbolAddress((void**)&qbias, g_qkvbias);
    cudaGetSymbolAddress((void**)&hp,    g_hp);
    cudaGetSymbolAddress((void**)&attnp, g_attnp);
    cudaGetSymbolAddress((void**)&actp,  g_actp);
    cudaGetSymbolAddress((void**)&wqp,   g_wqp);
    cudaGetSymbolAddress((void**)&wpp,   g_wpp);
    cudaGetSymbolAddress((void**)&w1p,   g_w1p);
    cudaGetSymbolAddress((void**)&w2p,   g_w2p);

    const int TTT_SMEM = (16384 + 64*5 + 256) * 4;
    cudaFuncSetAttribute(ttt_kernel, cudaFuncAttributeMaxDynamicSharedMemorySize, TTT_SMEM);

    // weight conversions (fp32 -> packed hi/lo bf16)
    convert_pack<<<(3*CC*CC + 255)/256, 256>>>(qkv_w, wqp, 3*CC*CC);
    convert_pack<<<(CC*CC   + 255)/256, 256>>>(proj_w, wpp, CC*CC);
    convert_pack<<<(4*CC*CC + 255)/256, 256>>>(fc1_w, w1p, 4*CC*CC);
    convert_pack<<<(CC*4*CC + 255)/256, 256>>>(fc2_w, w2p, CC*4*CC);
    qkvbias_kernel<<<(3*CC + 255)/256, 256>>>(q_bias, v_bias, qbias);

    // LN1 + eta
    ln_kernel<<<ROWS, 256>>>(x, n1w, n1b, lr_w, lr_b, hp, etap);
    // qkv = h @ qkv_w^T + qkvbias
    gemm_mma<0><<<dim3(3*CC/BN, ROWS/BM), 256>>>(
        (const uint4*)hp, (const uint4*)wqp, qbias, nullptr, qkvb, nullptr, ROWS, 3*CC, CC);
    // TTT attention
    ttt_kernel<<<BB*NH, 256, TTT_SMEM>>>(qkvb, etap, W1, b1, ttt_w, ttt_b, attnp);
    // x2 = x + attn @ proj_w^T + proj_b
    gemm_mma<1><<<dim3(CC/BN, ROWS/BM), 256>>>(
        (const uint4*)attnp, (const uint4*)wpp, proj_b, x, x2, nullptr, ROWS, CC, CC);
    // LN2
    ln_kernel<<<ROWS, 256>>>(x2, n2w, n2b, nullptr, nullptr, hp, nullptr);
    // act = gelu(h2 @ fc1_w^T + fc1_b), packed
    gemm_mma<2><<<dim3(4*CC/BN, ROWS/BM), 256>>>(
        (const uint4*)hp, (const uint4*)w1p, fc1_b, nullptr, nullptr, actp, ROWS, 4*CC, CC);
    // out = x2 + act @ fc2_w^T + fc2_b
    gemm_mma<1><<<dim3(CC/BN, ROWS/BM), 256>>>(
        (const uint4*)actp, (const uint4*)w2p, fc2_b, x2, out, nullptr, ROWS, CC, 4*CC);
}

// round 5
// speedup vs baseline: 2.0039x; 1.0228x over previous
#include <cuda_runtime.h>
#include <cuda_bf16.h>
#include <math.h>
#include <stdint.h>

#define BB 16
#define NN 1024
#define CC 768
#define NH 12
#define HD 64
#define ROWS (BB*NN)        // 16384

// GEMM tiling (mma.sync + cp.async path)
#define BM 128
#define BN 128
#define BK 32               // k elements per chunk
#define PITCH 40            // smem row pitch (bf16): 80B rows, 16B-aligned, conflict-free
#define NSTAGE 3
#define PLANE_ELEMS (128*PITCH)                 // 5120
#define GEMM_SMEM (NSTAGE*4*PLANE_ELEMS*2)      // 122880 B

// ---------------- device scratch ----------------
__device__ float g_qkv[ROWS*3*CC];      // qkv projections fp32
__device__ float g_eta[BB*NH*NN];
__device__ float g_x2[ROWS*CC];         // x after proj residual (fp32)
__device__ float g_qkvbias[3*CC];
__device__ __align__(16) __nv_bfloat16 g_hhi[ROWS*CC],    g_hlo[ROWS*CC];     // h / h2 planes
__device__ __align__(16) __nv_bfloat16 g_attnhi[ROWS*CC], g_attnlo[ROWS*CC];
__device__ __align__(16) __nv_bfloat16 g_acthi[ROWS*4*CC], g_actlo[ROWS*4*CC];
__device__ __align__(16) __nv_bfloat16 g_wqhi[3*CC*CC],  g_wqlo[3*CC*CC];
__device__ __align__(16) __nv_bfloat16 g_wphi[CC*CC],    g_wplo[CC*CC];
__device__ __align__(16) __nv_bfloat16 g_w1hi[4*CC*CC],  g_w1lo[4*CC*CC];
__device__ __align__(16) __nv_bfloat16 g_w2hi[CC*4*CC],  g_w2lo[CC*4*CC];

// ---------------- helpers ----------------
__device__ __forceinline__ float warpsum(float v) {
#pragma unroll
    for (int o = 16; o > 0; o >>= 1) v += __shfl_xor_sync(0xffffffffu, v, o);
    return v;
}
__device__ __forceinline__ void split2(float v, __nv_bfloat16& hi, __nv_bfloat16& lo) {
    hi = __float2bfloat16(v);
    lo = __float2bfloat16(v - __bfloat162float(hi));
}
__device__ __forceinline__ void mma16816(float* d, const uint32_t* a, const uint32_t* b) {
    asm volatile(
        "mma.sync.aligned.m16n8k16.row.col.f32.bf16.bf16.f32 "
        "{%0,%1,%2,%3}, {%4,%5,%6,%7}, {%8,%9}, {%0,%1,%2,%3};"
        : "+f"(d[0]), "+f"(d[1]), "+f"(d[2]), "+f"(d[3])
        : "r"(a[0]), "r"(a[1]), "r"(a[2]), "r"(a[3]), "r"(b[0]), "r"(b[1]));
}
__device__ __forceinline__ void cpasync16(uint32_t dst, const void* src) {
    asm volatile("cp.async.cg.shared.global [%0], [%1], 16;" :: "r"(dst), "l"(src));
}
__device__ __forceinline__ uint32_t smaddr(const void* p) {
    uint32_t a;
    asm("{ .reg .u64 t; cvta.to.shared.u64 t, %1; cvt.u32.u64 %0, t; }" : "=r"(a) : "l"(p));
    return a;
}

// ---------------- small elementwise kernels ----------------
__global__ void qkvbias_kernel(const float* __restrict__ qb,
                               const float* __restrict__ vb,
                               float* __restrict__ out) {
    int i = blockIdx.x * blockDim.x + threadIdx.x;
    if (i < 3*CC) out[i] = (i < CC) ? qb[i] : (i < 2*CC ? 0.0f : vb[i - 2*CC]);
}
__global__ void convert_split(const float* __restrict__ in,
                              __nv_bfloat16* __restrict__ hi,
                              __nv_bfloat16* __restrict__ lo, int n) {
    int i = blockIdx.x * blockDim.x + threadIdx.x;
    if (i < n) { __nv_bfloat16 h, l; split2(in[i], h, l); hi[i] = h; lo[i] = l; }
}

// ---------------- LayerNorm (+ optional eta), split planes out ----------------
__global__ void __launch_bounds__(256) ln_kernel(
    const float* __restrict__ x, const float* __restrict__ w, const float* __restrict__ bp,
    const float* __restrict__ lrw, const float* __restrict__ lrb,
    __nv_bfloat16* __restrict__ hhi, __nv_bfloat16* __restrict__ hlo,
    float* __restrict__ eta)
{
    __shared__ float redA[8], redB[8], pr[8*NH];
    int row = blockIdx.x;
    int tid = threadIdx.x, lane = tid & 31, warp = tid >> 5;
    const float* xr = x + (size_t)row * CC;
    float v0 = xr[tid], v1 = xr[tid+256], v2 = xr[tid+512];

    float s = warpsum(v0+v1+v2);
    if (lane == 0) redA[warp] = s;
    __syncthreads();
    float tot = 0.f;
#pragma unroll
    for (int i = 0; i < 8; i++) tot += redA[i];
    float mu = tot * (1.0f/CC);
    float d0 = v0-mu, d1 = v1-mu, d2 = v2-mu;
    float vsum = warpsum(d0*d0 + d1*d1 + d2*d2);
    if (lane == 0) redB[warp] = vsum;
    __syncthreads();
    float var = 0.f;
#pragma unroll
    for (int i = 0; i < 8; i++) var += redB[i];
    var *= (1.0f/CC);
    float rstd = rsqrtf(var + 1e-6f);

    float h0 = w[tid    ]*d0*rstd + bp[tid    ];
    float h1 = w[tid+256]*d1*rstd + bp[tid+256];
    float h2 = w[tid+512]*d2*rstd + bp[tid+512];
    size_t rb = (size_t)row * CC;
    __nv_bfloat16 hh, hl;
    split2(h0, hh, hl); hhi[rb+tid]     = hh; hlo[rb+tid]     = hl;
    split2(h1, hh, hl); hhi[rb+tid+256] = hh; hlo[rb+tid+256] = hl;
    split2(h2, hh, hl); hhi[rb+tid+512] = hh; hlo[rb+tid+512] = hl;

    if (eta) {
        float p[NH];
#pragma unroll
        for (int hh2 = 0; hh2 < NH; hh2++) {
            const float* lw = lrw + (size_t)hh2 * CC;
            p[hh2] = h0*lw[tid] + h1*lw[tid+256] + h2*lw[tid+512];
        }
#pragma unroll
        for (int hh2 = 0; hh2 < NH; hh2++) {
            float ps = warpsum(p[hh2]);
            if (lane == 0) pr[warp*NH + hh2] = ps;
        }
        __syncthreads();
        if (tid < NH) {
            float ss = 0.f;
#pragma unroll
            for (int wv = 0; wv < 8; wv++) ss += pr[wv*NH + tid];
            ss += lrb[tid];
            float sg = 1.0f / (1.0f + expf(-ss));
            int b = row >> 10, n = row & 1023;
            eta[((size_t)(b*NH + tid))*NN + n] = sg * (1.0f/HD);
        }
    }
}

// ---------------- cp.async pipelined split-bf16 GEMM NT ----------------
// C[M,Nn] = epi(A @ B^T + bias) where A = Ahi+Alo, B = Bhi+Blo (bf16 planes)
// EPI: 0 = fp32 out; 1 = +Res fp32 out; 2 = gelu, split planes out
template<int EPI>
__global__ void __launch_bounds__(256, 1) gemm_mma(
    const __nv_bfloat16* __restrict__ Ahi, const __nv_bfloat16* __restrict__ Alo,
    const __nv_bfloat16* __restrict__ Bhi, const __nv_bfloat16* __restrict__ Blo,
    const float* __restrict__ bias, const float* __restrict__ Res,
    float* __restrict__ Cout,
    __nv_bfloat16* __restrict__ Chi, __nv_bfloat16* __restrict__ Clo,
    int M, int Nn, int K)
{
    extern __shared__ __nv_bfloat16 smem[];
    uint32_t smbase = smaddr(smem);

    int tid = threadIdx.x;
    int lane = tid & 31, wid = tid >> 5;
    int wm = wid & 1, wn = wid >> 1;          // 2x4 warp grid, warp tile 64x32
    int g = lane >> 2, t4 = lane & 3;
    int bn = blockIdx.x * BN, bm = blockIdx.y * BM;
    const int nch = K / BK;

    const __nv_bfloat16* planes[4] = {
        Ahi + (size_t)bm*K, Alo + (size_t)bm*K,
        Bhi + (size_t)bn*K, Blo + (size_t)bn*K };

    // per-thread load coords: 512 16B-segs per plane, 2 iters of 256 threads
    int lrow0 = tid >> 2, lseg = tid & 3;

    float acc[4][4][4];
#pragma unroll
    for (int i = 0; i < 4; i++)
#pragma unroll
        for (int j = 0; j < 4; j++)
#pragma unroll
            for (int k = 0; k < 4; k++) acc[i][j][k] = 0.f;

#define ISSUE(stage, c) do {                                                    \
        int kb = (c) * BK;                                                      \
        _Pragma("unroll")                                                       \
        for (int p = 0; p < 4; p++) {                                           \
            _Pragma("unroll")                                                   \
            for (int it = 0; it < 2; it++) {                                    \
                int row = lrow0 + it*64;                                        \
                uint32_t dst = smbase +                                         \
                    (((stage)*4 + p)*PLANE_ELEMS + row*PITCH + lseg*8)*2;       \
                cpasync16(dst, planes[p] + (size_t)row*K + kb + lseg*8);        \
            }                                                                   \
        }                                                                       \
        asm volatile("cp.async.commit_group;" ::: "memory");                    \
    } while (0)

    // prologue: stages 0..NSTAGE-2
    ISSUE(0, 0);
    ISSUE(1, 1);

    for (int c = 0; c < nch; ++c) {
        int s = c % NSTAGE;
        asm volatile("cp.async.wait_group %0;" :: "n"(NSTAGE-2) : "memory");
        __syncthreads();
        int cn = c + NSTAGE - 1;
        if (cn < nch) ISSUE(cn % NSTAGE, cn);

        const __nv_bfloat16* pAhi = smem + (s*4 + 0)*PLANE_ELEMS;
        const __nv_bfloat16* pAlo = smem + (s*4 + 1)*PLANE_ELEMS;
        const __nv_bfloat16* pBhi = smem + (s*4 + 2)*PLANE_ELEMS;
        const __nv_bfloat16* pBlo = smem + (s*4 + 3)*PLANE_ELEMS;

#pragma unroll
        for (int ks = 0; ks < 2; ks++) {
            int kof = ks*16 + t4*2;
            uint32_t ah[4][4], al[4][4], bh[4][2], bl[4][2];
#pragma unroll
            for (int mt = 0; mt < 4; mt++) {
                int base = (wm*64 + mt*16 + g)*PITCH + kof;
                ah[mt][0] = *(const uint32_t*)&pAhi[base];
                ah[mt][1] = *(const uint32_t*)&pAhi[base + 8*PITCH];
                ah[mt][2] = *(const uint32_t*)&pAhi[base + 8];
                ah[mt][3] = *(const uint32_t*)&pAhi[base + 8*PITCH + 8];
                al[mt][0] = *(const uint32_t*)&pAlo[base];
                al[mt][1] = *(const uint32_t*)&pAlo[base + 8*PITCH];
                al[mt][2] = *(const uint32_t*)&pAlo[base + 8];
                al[mt][3] = *(const uint32_t*)&pAlo[base + 8*PITCH + 8];
            }
#pragma unroll
            for (int nt = 0; nt < 4; nt++) {
                int base = (wn*32 + nt*8 + g)*PITCH + kof;
                bh[nt][0] = *(const uint32_t*)&pBhi[base];
                bh[nt][1] = *(const uint32_t*)&pBhi[base + 8];
                bl[nt][0] = *(const uint32_t*)&pBlo[base];
                bl[nt][1] = *(const uint32_t*)&pBlo[base + 8];
            }
#pragma unroll
            for (int mt = 0; mt < 4; mt++)
#pragma unroll
                for (int nt = 0; nt < 4; nt++) {
                    mma16816(acc[mt][nt], ah[mt], bh[nt]);
                    mma16816(acc[mt][nt], ah[mt], bl[nt]);
                    mma16816(acc[mt][nt], al[mt], bh[nt]);
                }
        }
    }
#undef ISSUE

    // epilogue: direct register -> global
#pragma unroll
    for (int mt = 0; mt < 4; mt++) {
#pragma unroll
        for (int nt = 0; nt < 4; nt++) {
            int r0 = bm + wm*64 + mt*16 + g;
            int c0 = bn + wn*32 + nt*8 + t4*2;
            float b0 = bias[c0], b1 = bias[c0+1];
#pragma unroll
            for (int half = 0; half < 2; half++) {
                int r = r0 + half*8;
                size_t gi = (size_t)r * Nn + c0;
                float v0 = acc[mt][nt][half*2]     + b0;
                float v1 = acc[mt][nt][half*2 + 1] + b1;
                if (EPI == 1) { v0 += Res[gi]; v1 += Res[gi+1]; }
                if (EPI == 2) {
                    v0 = 0.5f*v0*(1.0f + erff(v0*0.70710678118654752f));
                    v1 = 0.5f*v1*(1.0f + erff(v1*0.70710678118654752f));
                    __nv_bfloat16 hh, hl;
                    split2(v0, hh, hl); Chi[gi]   = hh; Clo[gi]   = hl;
                    split2(v1, hh, hl); Chi[gi+1] = hh; Clo[gi+1] = hl;
                } else {
                    Cout[gi]   = v0;
                    Cout[gi+1] = v1;
                }
            }
        }
    }
}

// ---------------- TTT kernel: one block per (b,h) ----------------
__global__ void __launch_bounds__(256) ttt_kernel(
    const float* __restrict__ qkv, const float* __restrict__ eta,
    const float* __restrict__ W1g, const float* __restrict__ b1g,
    const float* __restrict__ tttw, const float* __restrict__ tttb,
    __nv_bfloat16* __restrict__ attnhi, __nv_bfloat16* __restrict__ attnlo)
{
    extern __shared__ float sm[];
    float* sW1  = sm;            // 4096 (becomes W1_bar)
    float* sK   = sm + 4096;
    float* sV   = sm + 8192;
    float* sZ   = sm + 12288;
    float* sEta = sm + 16384;    // 64
    float* sGw  = sEta + 64;
    float* sGb  = sGw + 64;
    float* sB1  = sGb + 64;
    float* sB1b = sB1 + 64;
    float* sBred= sB1b + 64;     // 256

    int bh = blockIdx.x;
    int b = bh / NH, h = bh % NH;
    int tid = threadIdx.x, tx = tid & 63, ty = tid >> 6;
    int lane = tid & 31, warp = tid >> 5;

    for (int i = tid; i < 4096; i += 256) sW1[i] = W1g[h*4096 + i];
    if (tid < 64) {
        sGw[tid] = tttw[h*64 + tid];
        sGb[tid] = tttb[h*64 + tid];
        sB1[tid] = b1g[h*64 + tid];
    }
    __syncthreads();

    const size_t rs = 3*CC;
    const float* qbase = qkv + (size_t)b*NN*rs + 0*CC + h*HD;
    const float* kbase = qkv + (size_t)b*NN*rs + 1*CC + h*HD;
    const float* vbase = qkv + (size_t)b*NN*rs + 2*CC + h*HD;

    float accW[16];
#pragma unroll
    for (int i = 0; i < 16; i++) accW[i] = 0.f;
    float accB = 0.f;

    for (int c = 0; c < 16; c++) {
        int n0 = c * 64;
        for (int i = tid; i < 4096; i += 256) {
            int n = i >> 6, e = i & 63;
            sK[i] = kbase[(size_t)(n0+n)*rs + e];
            sV[i] = vbase[(size_t)(n0+n)*rs + e];
        }
        if (tid < 64) sEta[tid] = eta[(size_t)bh*NN + n0 + tid];
        __syncthreads();

        {
            float az[16];
#pragma unroll
            for (int i = 0; i < 16; i++) az[i] = sB1[tx];
            for (int d = 0; d < 64; d++) {
                float w = sW1[d*64 + tx];
#pragma unroll
                for (int i = 0; i < 16; i++) az[i] += sK[(i*4 + ty)*64 + d] * w;
            }
#pragma unroll
            for (int i = 0; i < 16; i++) sZ[(i*4 + ty)*64 + tx] = az[i];
        }
        __syncthreads();

        for (int j = 0; j < 8; j++) {
            int n = warp + 8*j;
            float z0 = sZ[n*64 + lane], z1 = sZ[n*64 + lane + 32];
            float mu = warpsum(z0 + z1) * (1.0f/64);
            float d0 = z0 - mu, d1 = z1 - mu;
            float var = warpsum(d0*d0 + d1*d1) * (1.0f/64);
            float rstd = rsqrtf(var + 1e-6f);
            float xh0 = d0*rstd, xh1 = d1*rstd;
            float t0 = sV[n*64 + lane]      - sK[n*64 + lane];
            float t1 = sV[n*64 + lane + 32] - sK[n*64 + lane + 32];
            float g0 = sGw[lane], g1 = sGw[lane + 32];
            float gho0 = (g0*xh0 + sGb[lane]      - t0) * g0;
            float gho1 = (g1*xh1 + sGb[lane + 32] - t1) * g1;
            float sg  = warpsum(gho0 + gho1);
            float sgx = warpsum(gho0*xh0 + gho1*xh1);
            float e = sEta[n];
            float inv = rstd * (1.0f/64) * e;
            sZ[n*64 + lane]      = (64.f*gho0 - sg - xh0*sgx) * inv;
            sZ[n*64 + lane + 32] = (64.f*gho1 - sg - xh1*sgx) * inv;
        }
        __syncthreads();

        for (int n = 0; n < 64; n++) {
            float z = sZ[n*64 + tx];
            const float* kr = &sK[n*64 + ty*16];
#pragma unroll
            for (int i = 0; i < 16; i++) accW[i] += kr[i] * z;
            if ((n >> 4) == ty) accB += z;
        }
        __syncthreads();
    }

#pragma unroll
    for (int i = 0; i < 16; i++) sW1[(ty*16 + i)*64 + tx] -= accW[i];
    sBred[ty*64 + tx] = accB;
    __syncthreads();
    if (ty == 0)
        sB1b[tx] = sB1[tx] - (sBred[tx] + sBred[64+tx] + sBred[128+tx] + sBred[192+tx]);
    __syncthreads();

    for (int c = 0; c < 16; c++) {
        int n0 = c * 64;
        for (int i = tid; i < 4096; i += 256) {
            int n = i >> 6, e = i & 63;
            sK[i] = qbase[(size_t)(n0+n)*rs + e];
        }
        __syncthreads();
        {
            float az[16];
#pragma unroll
            for (int i = 0; i < 16; i++) az[i] = sB1b[tx];
            for (int d = 0; d < 64; d++) {
                float w = sW1[d*64 + tx];
#pragma unroll
                for (int i = 0; i < 16; i++) az[i] += sK[(i*4 + ty)*64 + d] * w;
            }
#pragma unroll
            for (int i = 0; i < 16; i++) sZ[(i*4 + ty)*64 + tx] = az[i];
        }
        __syncthreads();
        for (int j = 0; j < 8; j++) {
            int n = warp + 8*j;
            float z0 = sZ[n*64 + lane], z1 = sZ[n*64 + lane + 32];
            float mu = warpsum(z0 + z1) * (1.0f/64);
            float d0 = z0 - mu, d1 = z1 - mu;
            float var = warpsum(d0*d0 + d1*d1) * (1.0f/64);
            float rstd = rsqrtf(var + 1e-6f);
            float o0 = sK[n*64 + lane]      + sGw[lane]     *d0*rstd + sGb[lane];
            float o1 = sK[n*64 + lane + 32] + sGw[lane + 32]*d1*rstd + sGb[lane + 32];
            size_t orow = ((size_t)(b*NN + n0 + n))*CC + h*HD;
            __nv_bfloat16 hh, hl;
            split2(o0, hh, hl); attnhi[orow + lane]      = hh; attnlo[orow + lane]      = hl;
            split2(o1, hh, hl); attnhi[orow + lane + 32] = hh; attnlo[orow + lane + 32] = hl;
        }
        __syncthreads();
    }
}

// ---------------- launch ----------------
extern "C" void kernel_launch(void* const* d_in, const int* in_sizes, int n_in,
                              void* d_out, int out_size) {
    const float* x      = (const float*)d_in[0];
    const float* qkv_w  = (const float*)d_in[1];
    const float* q_bias = (const float*)d_in[2];
    const float* v_bias = (const float*)d_in[3];
    const float* proj_w = (const float*)d_in[4];
    const float* proj_b = (const float*)d_in[5];
    const float* lr_w   = (const float*)d_in[6];
    const float* lr_b   = (const float*)d_in[7];
    const float* W1     = (const float*)d_in[8];
    const float* b1     = (const float*)d_in[9];
    const float* ttt_w  = (const float*)d_in[10];
    const float* ttt_b  = (const float*)d_in[11];
    const float* n1w    = (const float*)d_in[12];
    const float* n1b    = (const float*)d_in[13];
    const float* n2w    = (const float*)d_in[14];
    const float* n2b    = (const float*)d_in[15];
    const float* fc1_w  = (const float*)d_in[16];
    const float* fc1_b  = (const float*)d_in[17];
    const float* fc2_w  = (const float*)d_in[18];
    const float* fc2_b  = (const float*)d_in[19];
    float* out = (float*)d_out;

    float *qkvb, *etap, *x2, *qbias;
    __nv_bfloat16 *hhi, *hlo, *athi, *atlo, *achi, *aclo;
    __nv_bfloat16 *wqhi, *wqlo, *wphi, *wplo, *w1hi, *w1lo, *w2hi, *w2lo;
    cudaGetSymbolAddress((void**)&qkvb,  g_qkv);
    cudaGetSymbolAddress((void**)&etap,  g_eta);
    cudaGetSymbolAddress((void**)&x2,    g_x2);
    cudaGetSymbolAddress((void**)&qbias, g_qkvbias);
    cudaGetSymbolAddress((void**)&hhi,   g_hhi);
    cudaGetSymbolAddress((void**)&hlo,   g_hlo);
    cudaGetSymbolAddress((void**)&athi,  g_attnhi);
    cudaGetSymbolAddress((void**)&atlo,  g_attnlo);
    cudaGetSymbolAddress((void**)&achi,  g_acthi);
    cudaGetSymbolAddress((void**)&aclo,  g_actlo);
    cudaGetSymbolAddress((void**)&wqhi,  g_wqhi);
    cudaGetSymbolAddress((void**)&wqlo,  g_wqlo);
    cudaGetSymbolAddress((void**)&wphi,  g_wphi);
    cudaGetSymbolAddress((void**)&wplo,  g_wplo);
    cudaGetSymbolAddress((void**)&w1hi,  g_w1hi);
    cudaGetSymbolAddress((void**)&w1lo,  g_w1lo);
    cudaGetSymbolAddress((void**)&w2hi,  g_w2hi);
    cudaGetSymbolAddress((void**)&w2lo,  g_w2lo);

    const int TTT_SMEM = (16384 + 64*5 + 256) * 4;
    cudaFuncSetAttribute(ttt_kernel, cudaFuncAttributeMaxDynamicSharedMemorySize, TTT_SMEM);
    cudaFuncSetAttribute(gemm_mma<0>, cudaFuncAttributeMaxDynamicSharedMemorySize, GEMM_SMEM);
    cudaFuncSetAttribute(gemm_mma<1>, cudaFuncAttributeMaxDynamicSharedMemorySize, GEMM_SMEM);
    cudaFuncSetAttribute(gemm_mma<2>, cudaFuncAttributeMaxDynamicSharedMemorySize, GEMM_SMEM);

    // weight conversions (fp32 -> hi/lo planes)
    convert_split<<<(3*CC*CC + 255)/256, 256>>>(qkv_w, wqhi, wqlo, 3*CC*CC);
    convert_split<<<(CC*CC   + 255)/256, 256>>>(proj_w, wphi, wplo, CC*CC);
    convert_split<<<(4*CC*CC + 255)/256, 256>>>(fc1_w, w1hi, w1lo, 4*CC*CC);
    convert_split<<<(CC*4*CC + 255)/256, 256>>>(fc2_w, w2hi, w2lo, CC*4*CC);
    qkvbias_kernel<<<(3*CC + 255)/256, 256>>>(q_bias, v_bias, qbias);

    // LN1 + eta
    ln_kernel<<<ROWS, 256>>>(x, n1w, n1b, lr_w, lr_b, hhi, hlo, etap);
    // qkv = h @ qkv_w^T + qkvbias  (fp32 out for TTT)
    gemm_mma<0><<<dim3(3*CC/BN, ROWS/BM), 256, GEMM_SMEM>>>(
        hhi, hlo, wqhi, wqlo, qbias, nullptr, qkvb, nullptr, nullptr, ROWS, 3*CC, CC);
    // TTT attention
    ttt_kernel<<<BB*NH, 256, TTT_SMEM>>>(qkvb, etap, W1, b1, ttt_w, ttt_b, athi, atlo);
    // x2 = x + attn @ proj_w^T + proj_b
    gemm_mma<1><<<dim3(CC/BN, ROWS/BM), 256, GEMM_SMEM>>>(
        athi, atlo, wphi, wplo, proj_b, x, x2, nullptr, nullptr, ROWS, CC, CC);
    // LN2
    ln_kernel<<<ROWS, 256>>>(x2, n2w, n2b, nullptr, nullptr, hhi, hlo, nullptr);
    // act = gelu(h2 @ fc1_w^T + fc1_b), split planes
    gemm_mma<2><<<dim3(4*CC/BN, ROWS/BM), 256, GEMM_SMEM>>>(
        hhi, hlo, w1hi, w1lo, fc1_b, nullptr, nullptr, achi, aclo, ROWS, 4*CC, CC);
    // out = x2 + act @ fc2_w^T + fc2_b
    gemm_mma<1><<<dim3(CC/BN, ROWS/BM), 256, GEMM_SMEM>>>(
        achi, aclo, w2hi, w2lo, fc2_b, x2, out, nullptr, nullptr, ROWS, CC, 4*CC);
}